// round 17
// baseline (speedup 1.0000x reference)
#include <cuda_runtime.h>
#include <math.h>

#define NB 16
#define NN 512
#define NH 8
#define ND 32
#define NE 16
#define NHID 256
#define GHEADS 4
#define ATT_SCALE 0.17677669529663687f  // 32^-0.5

#define PSTRIDE 516   // P row stride in floats: multiple of 4 -> float4-aligned rows

// ---- packed fp32x2 helpers (attention kernel) ----
#define PACKF2(out, x) \
    asm("mov.b64 %0, {%1, %1};" : "=l"(out) : "r"(__float_as_uint(x)))
#define FMA2(d, a, b) \
    asm("fma.rn.f32x2 %0, %1, %2, %0;" : "+l"(d) : "l"(a), "l"(b))
#define UNPACKF2(lo, hi, v) do { unsigned int _u, _v;                         \
    asm("mov.b64 {%0, %1}, %2;" : "=r"(_u), "=r"(_v) : "l"(v));               \
    lo = __uint_as_float(_u); hi = __uint_as_float(_v); } while (0)

// ---- tf32 mma helpers ----
__device__ __forceinline__ void f2tf2(float x, unsigned int& hi, unsigned int& lo) {
    unsigned int h;
    asm("cvt.rna.tf32.f32 %0, %1;" : "=r"(h) : "f"(x));
    float l = x - __uint_as_float(h);   // exact: hi is x with truncated mantissa
    unsigned int lw;
    asm("cvt.rna.tf32.f32 %0, %1;" : "=r"(lw) : "f"(l));
    hi = h; lo = lw;
}

#define MMA_TF32(d, a, b) \
    asm("mma.sync.aligned.m16n8k8.row.col.f32.tf32.tf32.f32 " \
        "{%0,%1,%2,%3}, {%4,%5,%6,%7}, {%8,%9}, {%0,%1,%2,%3};" \
        : "+f"(d[0]), "+f"(d[1]), "+f"(d[2]), "+f"(d[3]) \
        : "r"(a[0]), "r"(a[1]), "r"(a[2]), "r"(a[3]), "r"(b[0]), "r"(b[1]))

// ---------------- device scratch (no allocations allowed) ----------------
__device__ float g_qh [NB*NH*NN*ND];   // [b][h][n][d]
__device__ float g_kh [NB*NH*NN*ND];
__device__ float g_vh [NB*NH*NN*ND];
__device__ float g_qhT[NB*NH*ND*NN];   // [b][h][d][n]
__device__ float g_khT[NB*NH*ND*NN];
__device__ float g_qke[NB*NH*NN*NE];   // qe + ke (both gathered at row i!)
__device__ float g_ao [NB*NN*NHID];    // attention output, [b][n][h*D+d]

struct QKVPtrs {
    const float* X[3];
    const float* W[3];
    const float* Bv[3];
};

// ---------------- 3xTF32 tensor-core GEMM mainloop: 128x64 tile ----------------
// 256 threads = 8 warps in 4(m) x 2(n) grid of 32x32 warp tiles, k-chunk 16.
// FRAGMENT-MAJOR smem: A cells uint4 [plane][mb(16-row)][ks][lane'], B cells uint2
// [plane][nb(8-col)][ks][lane'], lane' = (lane&3)*8 + (lane>>2). Mainloop fragment
// fetch = 1 LDS.128 / LDS.64 per fragment, conflict-free; staging STS <=2-way.
// Split: D += Ahi*Bhi + Ahi*Blo + Alo*Bhi  (same order as validated R15).
__device__ __forceinline__ void gemm_core_mma(const float* __restrict__ Xp,
                                              const float* __restrict__ W,
                                              uint4 (*sAf)[8][2][32],
                                              uint2 (*sBf)[8][2][32],
                                              float acc[2][4][4],
                                              int m0, int o0, int tid)
{
    int lane = tid & 31, w = tid >> 5;
    int wm = w & 3, wn = w >> 2;
    int lp = ((lane & 3) << 3) | (lane >> 2);   // fragment-cell permutation
    int lmA = tid >> 1, lkA = (tid & 1) * 8;    // A: 2 thr/row, 8 words each
    int lmB = tid >> 2, lkB = (tid & 3) * 4;    // B: 4 thr/row, 4 words each
    int mbA = lmA >> 4, r16 = lmA & 15, gA = r16 & 7, rh = r16 >> 3;
    int nbB = lmB >> 3, gB = lmB & 7;

    for (int kc = 0; kc < 256; kc += 16) {
        float4 v0 = *(const float4*)&Xp[(m0 + lmA) * 256 + kc + lkA];
        float4 v1 = *(const float4*)&Xp[(m0 + lmA) * 256 + kc + lkA + 4];
        float4 u0 = *(const float4*)&W [(o0 + lmB) * 256 + kc + lkB];
        __syncthreads();
        {
            float av[8] = {v0.x, v0.y, v0.z, v0.w, v1.x, v1.y, v1.z, v1.w};
            #pragma unroll
            for (int i = 0; i < 8; i++) {
                int kck = lkA + i;                   // 0..15 within chunk
                int ks = kck >> 3, klo = kck & 7;
                int tig = klo & 3, wk = klo >> 2;
                unsigned int hi, lo;
                f2tf2(av[i], hi, lo);
                ((unsigned int*)&sAf[0][mbA][ks][(tig << 3) | gA])[rh + 2 * wk] = hi;
                ((unsigned int*)&sAf[1][mbA][ks][(tig << 3) | gA])[rh + 2 * wk] = lo;
            }
            float bv[4] = {u0.x, u0.y, u0.z, u0.w};
            #pragma unroll
            for (int i = 0; i < 4; i++) {
                int kck = lkB + i;
                int ks = kck >> 3, klo = kck & 7;
                int tig = klo & 3, wk = klo >> 2;
                unsigned int hi, lo;
                f2tf2(bv[i], hi, lo);
                ((unsigned int*)&sBf[0][nbB][ks][(tig << 3) | gB])[wk] = hi;
                ((unsigned int*)&sBf[1][nbB][ks][(tig << 3) | gB])[wk] = lo;
            }
        }
        __syncthreads();
        #pragma unroll
        for (int ks = 0; ks < 2; ks++) {
            unsigned int ah[2][4], al[2][4];
            #pragma unroll
            for (int f = 0; f < 2; f++) {
                uint4 t0 = sAf[0][wm * 2 + f][ks][lp];
                ah[f][0] = t0.x; ah[f][1] = t0.y; ah[f][2] = t0.z; ah[f][3] = t0.w;
                uint4 t1 = sAf[1][wm * 2 + f][ks][lp];
                al[f][0] = t1.x; al[f][1] = t1.y; al[f][2] = t1.z; al[f][3] = t1.w;
            }
            #pragma unroll
            for (int g = 0; g < 4; g++) {
                uint2 tb = sBf[0][wn * 4 + g][ks][lp];
                uint2 tl = sBf[1][wn * 4 + g][ks][lp];
                unsigned int bh[2] = {tb.x, tb.y};
                unsigned int bl[2] = {tl.x, tl.y};
                #pragma unroll
                for (int f = 0; f < 2; f++) {
                    MMA_TF32(acc[f][g], ah[f], bh);
                    MMA_TF32(acc[f][g], ah[f], bl);
                    MMA_TF32(acc[f][g], al[f], bh);
                }
            }
        }
    }
}

// ---------------- fused Q/K/V projection GEMM (blockIdx.z selects q/k/v) ----------------
__global__ __launch_bounds__(256) void qkv_gemm(QKVPtrs P)
{
    __shared__ uint4 sAf[2][8][2][32];   // 16 KB
    __shared__ uint2 sBf[2][8][2][32];   // 8 KB

    int which = blockIdx.z;
    int m0 = blockIdx.x * 128;
    int o0 = blockIdx.y * 64;
    int tid = threadIdx.x;
    int lane = tid & 31, w = tid >> 5;
    int wm = w & 3, wn = w >> 2;
    int gID = lane >> 2, tig = lane & 3;

    float acc[2][4][4];
    #pragma unroll
    for (int f = 0; f < 2; f++)
        #pragma unroll
        for (int g = 0; g < 4; g++)
            #pragma unroll
            for (int i = 0; i < 4; i++) acc[f][g][i] = 0.f;

    gemm_core_mma(P.X[which], P.W[which], sAf, sBf, acc, m0, o0, tid);

    float* dst  = (which == 0) ? g_qh : ((which == 1) ? g_kh : g_vh);
    float* dstT = (which == 0) ? g_qhT : g_khT;   // used only when which < 2
    #pragma unroll
    for (int g = 0; g < 4; g++) {
        int oo = o0 + wn * 32 + g * 8 + 2 * tig;
        float2 bb = *(const float2*)&P.Bv[which][oo];
        int h = oo >> 5, d = oo & (ND - 1);
        #pragma unroll
        for (int f = 0; f < 2; f++) {
            #pragma unroll
            for (int rr = 0; rr < 2; rr++) {
                int m = m0 + wm * 32 + f * 16 + rr * 8 + gID;
                float y0 = acc[f][g][rr * 2 + 0] + bb.x;
                float y1 = acc[f][g][rr * 2 + 1] + bb.y;
                int b = m >> 9, n = m & (NN - 1);
                *(float2*)&dst[(((b * NH + h) * NN) + n) * ND + d] = make_float2(y0, y1);
                if (which < 2) {
                    int base = ((b * NH + h) * ND + d) * NN + n;
                    dstT[base]      = y0;
                    dstT[base + NN] = y1;
                }
            }
        }
    }
}

// ---------------- output projection GEMM: out = g_ao @ Wo^T + bo ----------------
__global__ __launch_bounds__(256) void out_gemm(const float* __restrict__ W,
                                                const float* __restrict__ bias,
                                                float* __restrict__ out)
{
    __shared__ uint4 sAf[2][8][2][32];
    __shared__ uint2 sBf[2][8][2][32];

    int m0 = blockIdx.x * 128;
    int o0 = blockIdx.y * 64;
    int tid = threadIdx.x;
    int lane = tid & 31, w = tid >> 5;
    int wm = w & 3, wn = w >> 2;
    int gID = lane >> 2, tig = lane & 3;

    float acc[2][4][4];
    #pragma unroll
    for (int f = 0; f < 2; f++)
        #pragma unroll
        for (int g = 0; g < 4; g++)
            #pragma unroll
            for (int i = 0; i < 4; i++) acc[f][g][i] = 0.f;

    gemm_core_mma(g_ao, W, sAf, sBf, acc, m0, o0, tid);

    #pragma unroll
    for (int g = 0; g < 4; g++) {
        int oo = o0 + wn * 32 + g * 8 + 2 * tig;
        float2 bb = *(const float2*)&bias[oo];
        #pragma unroll
        for (int f = 0; f < 2; f++) {
            #pragma unroll
            for (int rr = 0; rr < 2; rr++) {
                int m = m0 + wm * 32 + f * 16 + rr * 8 + gID;
                float y0 = acc[f][g][rr * 2 + 0] + bb.x;
                float y1 = acc[f][g][rr * 2 + 1] + bb.y;
                *(float2*)&out[m * NHID + oo] = make_float2(y0, y1);
            }
        }
    }
}

// ---------------- combined edge-type score table: g_qke[b][h][n][e] ----------------
__global__ __launch_bounds__(256) void edge_kernel(const float* __restrict__ qemb,
                                                   const float* __restrict__ kemb)
{
    int bh = blockIdx.x;
    int h = bh & (NH - 1);
    __shared__ float sq[NE * ND], sk[NE * ND];
    int tid = threadIdx.x;
    for (int t = tid; t < NE * ND; t += 256) {
        int e = t >> 5, d = t & 31;
        sq[t] = qemb[e * (NH * ND) + h * ND + d];
        sk[t] = kemb[e * (NH * ND) + h * ND + d];
    }
    __syncthreads();

    int n = blockIdx.y * 256 + tid;
    const float4* q4 = (const float4*)&g_qh[((size_t)bh * NN + n) * ND];
    const float4* k4 = (const float4*)&g_kh[((size_t)bh * NN + n) * ND];

    float acc[NE];
    #pragma unroll
    for (int e = 0; e < NE; e++) acc[e] = 0.f;

    #pragma unroll
    for (int g = 0; g < 8; g++) {
        float4 qv = q4[g];
        float4 kv = k4[g];
        #pragma unroll
        for (int e = 0; e < NE; e++) {
            const float4 s1 = *(const float4*)&sq[e * ND + g * 4];
            const float4 s2 = *(const float4*)&sk[e * ND + g * 4];
            float a = acc[e];
            a = fmaf(qv.x, s1.x, a);
            a = fmaf(qv.y, s1.y, a);
            a = fmaf(qv.z, s1.z, a);
            a = fmaf(qv.w, s1.w, a);
            a = fmaf(kv.x, s2.x, a);
            a = fmaf(kv.y, s2.y, a);
            a = fmaf(kv.z, s2.z, a);
            a = fmaf(kv.w, s2.w, a);
            acc[e] = a;
        }
    }

    float4* out = (float4*)&g_qke[((size_t)bh * NN + n) * NE];
    out[0] = make_float4(acc[0],  acc[1],  acc[2],  acc[3]);
    out[1] = make_float4(acc[4],  acc[5],  acc[6],  acc[7]);
    out[2] = make_float4(acc[8],  acc[9],  acc[10], acc[11]);
    out[3] = make_float4(acc[12], acc[13], acc[14], acc[15]);
}

// ---------------- fused attention: one CTA = (b, h, 32-row i-tile) ----------------
// (best form: register scores, shuffle softmax, P over dead K^T, V from gmem/L2)
__global__ __launch_bounds__(256, 2) void attn_kernel(const int* __restrict__ edge_attr,
                                                      const int* __restrict__ mask,
                                                      const int* __restrict__ fmask)
{
    extern __shared__ float sm[];
    float* buf0 = sm;                 // 16512 floats: K^T [d][512], then P [32] stride 516
    float* sQT  = sm + 16512;         // [d][32]
    float* sQE  = sQT + 1024;         // [32][16]
    float* sMb  = sQE + 512;          // additive key mask (0 / -inf)

    int it = blockIdx.x, h = blockIdx.y, b = blockIdx.z;
    int bh = b * NH + h;
    int gi0 = it * 32;
    int tid = threadIdx.x;

    {   // K^T tile: contiguous 64KB copy
        const float4* srcK = (const float4*)(g_khT + (size_t)bh * ND * NN);
        float4* dstK = (float4*)buf0;
        for (int t = tid; t < 4096; t += 256) dstK[t] = srcK[t];
    }
    {   // Q^T 32x32 sub-tile
        const float* qT = g_qhT + (size_t)bh * ND * NN;
        for (int t = tid; t < 1024; t += 256)
            sQT[t] = qT[(t >> 5) * NN + gi0 + (t & 31)];
    }
    {   // combined edge table rows for this i-tile
        const float* src = g_qke + ((size_t)bh * NN + gi0) * NE;
        for (int t = tid; t < 512; t += 256) sQE[t] = src[t];
    }
    for (int t = tid; t < NN; t += 256)
        sMb[t] = mask[b * NN + t] ? 0.f : -INFINITY;
    __syncthreads();

    int tr = tid >> 5, tc = tid & 31;   // tr: i-group (warp id), tc: lane
    int i0 = tr * 4;
    const ulonglong2* KT2 = (const ulonglong2*)buf0;   // [d][128] col-pairs
    const float4*     QT4 = (const float4*)sQT;        // [d][8]
    bool focal = (h >= GHEADS);

    // ---- S = scale*(Q K^T + bias) + mask, kept in registers ----
    float S[4][16];   // [row a][pass*4 + c]
    #pragma unroll
    for (int pass = 0; pass < 4; pass++) {
        int jg = pass * 32 + tc;
        unsigned long long accP[4][2];
        #pragma unroll
        for (int a = 0; a < 4; a++) { accP[a][0] = 0ull; accP[a][1] = 0ull; }
        #pragma unroll 8
        for (int d = 0; d < 32; d++) {
            ulonglong2 k2 = KT2[d * 128 + jg];         // (c0,c1),(c2,c3)
            float4 q4 = QT4[d * 8 + tr];
            unsigned long long qs0, qs1, qs2, qs3;
            PACKF2(qs0, q4.x); PACKF2(qs1, q4.y); PACKF2(qs2, q4.z); PACKF2(qs3, q4.w);
            FMA2(accP[0][0], qs0, k2.x); FMA2(accP[0][1], qs0, k2.y);
            FMA2(accP[1][0], qs1, k2.x); FMA2(accP[1][1], qs1, k2.y);
            FMA2(accP[2][0], qs2, k2.x); FMA2(accP[2][1], qs2, k2.y);
            FMA2(accP[3][0], qs3, k2.x); FMA2(accP[3][1], qs3, k2.y);
        }
        int j0 = jg * 4;
        #pragma unroll
        for (int a = 0; a < 4; a++) {
            float ac0, ac1, ac2, ac3;
            UNPACKF2(ac0, ac1, accP[a][0]);
            UNPACKF2(ac2, ac3, accP[a][1]);
            int gi = gi0 + i0 + a;
            int4 e4 = *(const int4*)&edge_attr[((size_t)b * NN + gi) * NN + j0];
            float mb0, mb1, mb2, mb3;
            if (focal) {
                int4 f4 = *(const int4*)&fmask[((size_t)b * NN + gi) * NN + j0];
                mb0 = f4.x ? 0.f : -INFINITY;
                mb1 = f4.y ? 0.f : -INFINITY;
                mb2 = f4.z ? 0.f : -INFINITY;
                mb3 = f4.w ? 0.f : -INFINITY;
            } else {
                mb0 = sMb[j0]; mb1 = sMb[j0+1]; mb2 = sMb[j0+2]; mb3 = sMb[j0+3];
            }
            const float* qe = &sQE[(i0 + a) * NE];
            S[a][pass*4+0] = (ac0 + qe[e4.x]) * ATT_SCALE + mb0;
            S[a][pass*4+1] = (ac1 + qe[e4.y]) * ATT_SCALE + mb1;
            S[a][pass*4+2] = (ac2 + qe[e4.z]) * ATT_SCALE + mb2;
            S[a][pass*4+3] = (ac3 + qe[e4.w]) * ATT_SCALE + mb3;
        }
    }

    // ---- softmax fully in registers: row a is spread over this warp's 32 lanes ----
    #pragma unroll
    for (int a = 0; a < 4; a++) {
        float m = S[a][0];
        #pragma unroll
        for (int c = 1; c < 16; c++) m = fmaxf(m, S[a][c]);
        m = fmaxf(m, __shfl_xor_sync(0xffffffffu, m, 16));
        m = fmaxf(m, __shfl_xor_sync(0xffffffffu, m, 8));
        m = fmaxf(m, __shfl_xor_sync(0xffffffffu, m, 4));
        m = fmaxf(m, __shfl_xor_sync(0xffffffffu, m, 2));
        m = fmaxf(m, __shfl_xor_sync(0xffffffffu, m, 1));
        float l = 0.f;
        #pragma unroll
        for (int c = 0; c < 16; c++) {
            float p = __expf(S[a][c] - m);
            S[a][c] = p;
            l += p;
        }
        l += __shfl_xor_sync(0xffffffffu, l, 16);
        l += __shfl_xor_sync(0xffffffffu, l, 8);
        l += __shfl_xor_sync(0xffffffffu, l, 4);
        l += __shfl_xor_sync(0xffffffffu, l, 2);
        l += __shfl_xor_sync(0xffffffffu, l, 1);
        float inv = 1.f / l;
        #pragma unroll
        for (int c = 0; c < 16; c++) S[a][c] *= inv;
    }

    __syncthreads();   // all warps done reading K^T -> safe to overwrite with P

    // ---- write normalized P over the dead K^T buffer, [i][j] stride PSTRIDE ----
    #pragma unroll
    for (int pass = 0; pass < 4; pass++) {
        int j0 = (pass * 32 + tc) * 4;
        #pragma unroll
        for (int a = 0; a < 4; a++)
            *(float4*)&buf0[(i0 + a) * PSTRIDE + j0] =
                make_float4(S[a][pass*4+0], S[a][pass*4+1], S[a][pass*4+2], S[a][pass*4+3]);
    }
    __syncwarp();   // PV reads only this warp's own P rows -> warp-local ordering suffices

    // ---- O = P V (f32x2): thread = 4 i-rows x 4 d-cols, 4-way j split; V from gmem ----
    {
        int dg = tc & 7, js = tc >> 3;
        const ulonglong2* V2 = (const ulonglong2*)(g_vh + (size_t)bh * NN * ND);  // [j][8]
        unsigned long long oP[4][2];
        #pragma unroll
        for (int a = 0; a < 4; a++) { oP[a][0] = 0ull; oP[a][1] = 0ull; }
        #pragma unroll 8
        for (int j = js; j < NN; j += 4) {
            ulonglong2 vv = V2[j * 8 + dg];            // (d0,d1),(d2,d3)
            float p0 = buf0[(i0+0) * PSTRIDE + j];
            float p1 = buf0[(i0+1) * PSTRIDE + j];
            float p2 = buf0[(i0+2) * PSTRIDE + j];
            float p3 = buf0[(i0+3) * PSTRIDE + j];
            unsigned long long ps0, ps1, ps2, ps3;
            PACKF2(ps0, p0); PACKF2(ps1, p1); PACKF2(ps2, p2); PACKF2(ps3, p3);
            FMA2(oP[0][0], ps0, vv.x); FMA2(oP[0][1], ps0, vv.y);
            FMA2(oP[1][0], ps1, vv.x); FMA2(oP[1][1], ps1, vv.y);
            FMA2(oP[2][0], ps2, vv.x); FMA2(oP[2][1], ps2, vv.y);
            FMA2(oP[3][0], ps3, vv.x); FMA2(oP[3][1], ps3, vv.y);
        }
        float4 o0, o1, o2, o3;
        UNPACKF2(o0.x, o0.y, oP[0][0]); UNPACKF2(o0.z, o0.w, oP[0][1]);
        UNPACKF2(o1.x, o1.y, oP[1][0]); UNPACKF2(o1.z, o1.w, oP[1][1]);
        UNPACKF2(o2.x, o2.y, oP[2][0]); UNPACKF2(o2.z, o2.w, oP[2][1]);
        UNPACKF2(o3.x, o3.y, oP[3][0]); UNPACKF2(o3.z, o3.w, oP[3][1]);
        #define WRED(v) \
            v.x += __shfl_xor_sync(0xffffffffu, v.x, 8);  v.x += __shfl_xor_sync(0xffffffffu, v.x, 16); \
            v.y += __shfl_xor_sync(0xffffffffu, v.y, 8);  v.y += __shfl_xor_sync(0xffffffffu, v.y, 16); \
            v.z += __shfl_xor_sync(0xffffffffu, v.z, 8);  v.z += __shfl_xor_sync(0xffffffffu, v.z, 16); \
            v.w += __shfl_xor_sync(0xffffffffu, v.w, 8);  v.w += __shfl_xor_sync(0xffffffffu, v.w, 16);
        WRED(o0) WRED(o1) WRED(o2) WRED(o3)
        #undef WRED
        if (js == 0) {
            int col = h * ND + dg * 4;
            size_t rb = ((size_t)b * NN + gi0 + i0) * NHID;
            *(float4*)&g_ao[rb            + col] = o0;
            *(float4*)&g_ao[rb +     NHID + col] = o1;
            *(float4*)&g_ao[rb + 2 * NHID + col] = o2;
            *(float4*)&g_ao[rb + 3 * NHID + col] = o3;
        }
    }
}

// ---------------- launch ----------------
extern "C" void kernel_launch(void* const* d_in, const int* in_sizes, int n_in,
                              void* d_out, int out_size)
{
    const float* q    = (const float*)d_in[0];
    const float* k    = (const float*)d_in[1];
    const float* v    = (const float*)d_in[2];
    const float* qemb = (const float*)d_in[3];
    const float* kemb = (const float*)d_in[4];
    const int*   eatt = (const int*)d_in[5];
    const int*   mask  = (const int*)d_in[6];
    const int*   fmask = (const int*)d_in[7];
    const float* Wq = (const float*)d_in[8];
    const float* bq = (const float*)d_in[9];
    const float* Wk = (const float*)d_in[10];
    const float* bk = (const float*)d_in[11];
    const float* Wv = (const float*)d_in[12];
    const float* bv = (const float*)d_in[13];
    const float* Wo = (const float*)d_in[14];
    const float* bo = (const float*)d_in[15];
    float* out = (float*)d_out;

    QKVPtrs P;
    P.X[0] = q;  P.X[1] = k;  P.X[2] = v;
    P.W[0] = Wq; P.W[1] = Wk; P.W[2] = Wv;
    P.Bv[0] = bq; P.Bv[1] = bk; P.Bv[2] = bv;

    qkv_gemm<<<dim3(64, 4, 3), 256>>>(P);

    edge_kernel<<<dim3(NB * NH, 2), 256>>>(qemb, kemb);

    int smem_bytes = (16512 + 1024 + 512 + 512) * 4;  // 74,240 B -> 2 CTAs/SM
    cudaFuncSetAttribute(attn_kernel, cudaFuncAttributeMaxDynamicSharedMemorySize, smem_bytes);
    attn_kernel<<<dim3(NN / 32, NH, NB), 256, smem_bytes>>>(eatt, mask, fmask);

    out_gemm<<<dim3(64, 4), 256>>>(Wo, bo, out);
}